// round 1
// baseline (speedup 1.0000x reference)
#include <cuda_runtime.h>

// Problem constants
#define BB   256   // batch
#define NN   196   // tokens
#define DD   768   // dim
#define PP   32    // pool size
#define LL   4     // patches per prompt image (2x2)
#define TOPK 5
#define MM   128   // PP*LL rows of patch-embed GEMM
#define KDIM 768   // 3*16*16

// Output layout (flattened tuple, float32):
//   prompted_embedding (256,216,768) | reduce_sim (1) | similarity (256,32) | idx (256,5)
#define O_RS  (42467328ll)
#define O_SIM (O_RS + 1)
#define O_IDX (O_SIM + (long long)BB * PP)

// Scratch (static device globals — no allocation allowed)
__device__ float g_pembed[MM * DD];   // patch-embed result (128,768)
__device__ float g_mean[BB * DD];     // per-batch mean of x_embed
__device__ float g_pnorm[PP * DD];    // l2-normalized prompt_key
__device__ int   g_idx[BB * TOPK];

// ---------------------------------------------------------------------------
// Mega kernel: three block roles.
//   blocks [0,48):  patch-embed GEMM  (M=128,N=768,K=768), 32x64 tiles
//   block  48:      prompt_key L2 normalize
//   blocks [49,305): per-batch copy x_embed -> out rows [20,216) + mean accum
// GEMM blocks are first so they start in wave 1 and hide under the HBM copy.
// ---------------------------------------------------------------------------
__global__ __launch_bounds__(256) void mega_kernel(
    const float* __restrict__ x,       // (256,196,768)
    const float* __restrict__ prompt,  // (32,3,32,32)
    const float* __restrict__ pkey,    // (32,768)
    const float* __restrict__ w,       // (768,3,16,16) == (768, 768) row-major
    const float* __restrict__ bias,    // (768)
    float* __restrict__ out)
{
    const int bx = blockIdx.x;
    const int t  = threadIdx.x;

    if (bx < 48) {
        // ---- patch-embed GEMM: out[m,d] = sum_k A[m,k]*W[d,k] + bias[d]
        // m = p*4 + l (l = py*2+px), k = c*256 + i*16 + j
        __shared__ float As[32][33];
        __shared__ float Ws[64][33];
        const int m0 = (bx / 12) * 32;
        const int n0 = (bx % 12) * 64;
        const int tx = t & 15;    // 4 output cols each
        const int ty = t >> 4;    // 2 output rows each
        float acc[2][4] = {{0.f,0.f,0.f,0.f},{0.f,0.f,0.f,0.f}};

        const float4* w4 = reinterpret_cast<const float4*>(w);

        for (int k0 = 0; k0 < KDIM; k0 += 32) {
            // load A tile (32 m x 32 k) from the strided conv-patch layout
            #pragma unroll
            for (int s = 0; s < 4; s++) {
                int e  = s * 256 + t;
                int mm = e >> 5;
                int kk = e & 31;
                int m  = m0 + mm;
                int p  = m >> 2;
                int l  = m & 3;
                int py = l >> 1, px = l & 1;
                int k  = k0 + kk;
                int c  = k >> 8;
                int rem = k & 255;
                int ii = rem >> 4, jj = rem & 15;
                As[mm][kk] = prompt[((size_t)(p * 3 + c) * 32 + py * 16 + ii) * 32
                                    + px * 16 + jj];
            }
            // load W tile (64 d x 32 k), vectorized
            #pragma unroll
            for (int s = 0; s < 2; s++) {
                int v  = s * 256 + t;        // 0..511
                int dd = v >> 3;             // 0..63
                int kv = v & 7;              // float4 index within the 32-k chunk
                float4 f = w4[(size_t)(n0 + dd) * 192 + (k0 >> 2) + kv];
                Ws[dd][kv * 4 + 0] = f.x;
                Ws[dd][kv * 4 + 1] = f.y;
                Ws[dd][kv * 4 + 2] = f.z;
                Ws[dd][kv * 4 + 3] = f.w;
            }
            __syncthreads();
            #pragma unroll
            for (int kk = 0; kk < 32; kk++) {
                float a0 = As[ty * 2 + 0][kk];
                float a1 = As[ty * 2 + 1][kk];
                #pragma unroll
                for (int j = 0; j < 4; j++) {
                    float wv = Ws[tx * 4 + j][kk];
                    acc[0][j] += a0 * wv;
                    acc[1][j] += a1 * wv;
                }
            }
            __syncthreads();
        }
        #pragma unroll
        for (int r = 0; r < 2; r++) {
            #pragma unroll
            for (int j = 0; j < 4; j++) {
                int m = m0 + ty * 2 + r;
                int d = n0 + tx * 4 + j;
                g_pembed[m * DD + d] = acc[r][j] + bias[d];
            }
        }
    } else if (bx == 48) {
        // ---- prompt_key L2 normalize: 8 warps x 4 rows
        int warp = t >> 5, lane = t & 31;
        for (int p = warp; p < PP; p += 8) {
            const float* row = pkey + (size_t)p * DD;
            float sq = 0.f;
            for (int k = lane; k < DD; k += 32) { float v = row[k]; sq += v * v; }
            #pragma unroll
            for (int o = 16; o; o >>= 1) sq += __shfl_xor_sync(0xffffffffu, sq, o);
            float rs = rsqrtf(fmaxf(sq, 1e-12f));
            for (int k = lane; k < DD; k += 32) g_pnorm[p * DD + k] = row[k] * rs;
        }
    } else {
        // ---- copy x_embed row-block to output + accumulate mean (fused read)
        int b = bx - 49;
        if (t < 192) {
            const float4* src = reinterpret_cast<const float4*>(x)
                                + (size_t)b * NN * 192 + t;
            float4* dst = reinterpret_cast<float4*>(out)
                          + ((size_t)b * 216 + 20) * 192 + t;
            float4 acc = make_float4(0.f, 0.f, 0.f, 0.f);
            #pragma unroll 1
            for (int n = 0; n < NN; n += 7) {     // 196 = 28 * 7, deep MLP
                float4 v[7];
                #pragma unroll
                for (int u = 0; u < 7; u++) v[u] = src[(size_t)(n + u) * 192];
                #pragma unroll
                for (int u = 0; u < 7; u++) {
                    dst[(size_t)(n + u) * 192] = v[u];
                    acc.x += v[u].x; acc.y += v[u].y;
                    acc.z += v[u].z; acc.w += v[u].w;
                }
            }
            const float inv = 1.0f / 196.0f;
            acc.x *= inv; acc.y *= inv; acc.z *= inv; acc.w *= inv;
            reinterpret_cast<float4*>(g_mean)[(size_t)b * 192 + t] = acc;
        }
    }
}

// ---------------------------------------------------------------------------
// Similarity: per-batch block. Normalizes mean row on the fly (sim = rs * dot).
// ---------------------------------------------------------------------------
__global__ __launch_bounds__(256) void sim_kernel(float* __restrict__ out)
{
    __shared__ float sx[DD];
    __shared__ float red[256];
    const int b = blockIdx.x, t = threadIdx.x;

    float sq = 0.f;
    for (int k = t; k < DD; k += 256) {
        float v = g_mean[(size_t)b * DD + k];
        sx[k] = v;
        sq += v * v;
    }
    red[t] = sq;
    __syncthreads();
    for (int s = 128; s; s >>= 1) {
        if (t < s) red[t] += red[t + s];
        __syncthreads();
    }
    float rs = rsqrtf(fmaxf(red[0], 1e-12f));

    int warp = t >> 5, lane = t & 31;
    for (int p = warp; p < PP; p += 8) {
        const float* pn = g_pnorm + (size_t)p * DD;
        float dot = 0.f;
        for (int k = lane; k < DD; k += 32) dot += sx[k] * pn[k];
        #pragma unroll
        for (int o = 16; o; o >>= 1) dot += __shfl_xor_sync(0xffffffffu, dot, o);
        if (lane == 0) out[O_SIM + (size_t)b * PP + p] = dot * rs;
    }
}

// ---------------------------------------------------------------------------
// Top-5 per batch row (lax.top_k tie semantics: lower index wins) + reduce_sim
// Single block: thread b handles row b.
// ---------------------------------------------------------------------------
__global__ __launch_bounds__(256) void topk_kernel(float* __restrict__ out)
{
    __shared__ float red[256];
    const int b = threadIdx.x;
    const float* sim = out + O_SIM + (size_t)b * PP;

    float vals[PP];
    #pragma unroll
    for (int p = 0; p < PP; p++) vals[p] = sim[p];

    float lsum = 0.f;
    unsigned mask = 0u;
    #pragma unroll
    for (int k = 0; k < TOPK; k++) {
        float best = -__int_as_float(0x7f800000);  // -inf
        int bi = 0;
        #pragma unroll
        for (int p = 0; p < PP; p++) {
            bool ok = !((mask >> p) & 1u) && (vals[p] > best);
            best = ok ? vals[p] : best;
            bi   = ok ? p : bi;
        }
        mask |= 1u << bi;
        g_idx[b * TOPK + k] = bi;
        out[O_IDX + (size_t)b * TOPK + k] = (float)bi;
        lsum += best;
    }
    red[b] = lsum;
    __syncthreads();
    for (int s = 128; s; s >>= 1) {
        if (b < s) red[b] += red[b + s];
        __syncthreads();
    }
    if (b == 0) out[O_RS] = red[0] / 256.0f;
}

// ---------------------------------------------------------------------------
// Gather: out rows [0,20) per batch = prompt_embed[idx[b, j/4]][j%4]
// One block per (b, j) row; 192 threads x float4.
// ---------------------------------------------------------------------------
__global__ __launch_bounds__(192) void gather_kernel(float* __restrict__ out)
{
    const int blk = blockIdx.x;     // 0..5119
    const int b = blk / 20;
    const int j = blk % 20;
    const int i = g_idx[b * TOPK + (j >> 2)];
    const int row = i * 4 + (j & 3);
    const float4* src = reinterpret_cast<const float4*>(g_pembed) + (size_t)row * 192;
    float4* dst = reinterpret_cast<float4*>(out) + ((size_t)b * 216 + j) * 192;
    dst[threadIdx.x] = src[threadIdx.x];
}

// ---------------------------------------------------------------------------
extern "C" void kernel_launch(void* const* d_in, const int* in_sizes, int n_in,
                              void* d_out, int out_size)
{
    const float* x      = (const float*)d_in[0];  // x_embed  (256,196,768)
    const float* prompt = (const float*)d_in[1];  // prompt   (32,3,32,32)
    const float* pkey   = (const float*)d_in[2];  // prompt_key (32,768)
    const float* w      = (const float*)d_in[3];  // conv_w   (768,3,16,16)
    const float* bias   = (const float*)d_in[4];  // conv_b   (768)
    float* out = (float*)d_out;

    mega_kernel<<<49 + BB, 256>>>(x, prompt, pkey, w, bias, out);
    sim_kernel<<<BB, 256>>>(out);
    topk_kernel<<<1, 256>>>(out);
    gather_kernel<<<BB * 20, 192>>>(out);
}

// round 2
// speedup vs baseline: 1.2698x; 1.2698x over previous
#include <cuda_runtime.h>

// Problem constants
#define BB   256   // batch
#define NN   196   // tokens
#define DD   768   // dim
#define PP   32    // pool size
#define TOPK 5
#define MM   128   // PP*4 rows of patch-embed GEMM
#define KDIM 768   // 3*16*16

// Output layout (flattened tuple, float32):
//   prompted_embedding (256,216,768) | reduce_sim (1) | similarity (256,32) | idx (256,5)
#define O_RS  (42467328ll)
#define O_SIM (O_RS + 1)
#define O_IDX (O_SIM + (long long)BB * PP)

// Scratch (static device globals — no allocation allowed)
__device__ float g_pembed[MM * DD];   // patch-embed result (128,768)
__device__ float g_mean[BB * DD];     // per-batch mean of x_embed
__device__ float g_pnorm[PP * DD];    // l2-normalized prompt_key
__device__ float g_rs[BB];            // per-batch top-5 sim sums
__device__ int   g_counter;           // last-block arrival counter (reset by winner)

// ---------------------------------------------------------------------------
// Mega kernel: three block roles.
//   blocks [0,48):  patch-embed GEMM  (M=128,N=768,K=768), 32x64 tiles
//   block  48:      prompt_key L2 normalize
//   blocks [49,305): per-batch copy x_embed -> out rows [20,216) + mean accum
// GEMM blocks first so they start in wave 1 and hide under the HBM-bound copy.
// ---------------------------------------------------------------------------
__global__ __launch_bounds__(256) void mega_kernel(
    const float* __restrict__ x,       // (256,196,768)
    const float* __restrict__ prompt,  // (32,3,32,32)
    const float* __restrict__ pkey,    // (32,768)
    const float* __restrict__ w,       // (768,3,16,16) == (768,768) row-major
    const float* __restrict__ bias,    // (768)
    float* __restrict__ out)
{
    const int bx = blockIdx.x;
    const int t  = threadIdx.x;

    if (bx < 48) {
        // ---- patch-embed GEMM: out[m,d] = sum_k A[m,k]*W[d,k] + bias[d]
        __shared__ float As[32][33];
        __shared__ float Ws[64][33];
        const int m0 = (bx / 12) * 32;
        const int n0 = (bx % 12) * 64;
        const int tx = t & 15;    // 4 output cols each
        const int ty = t >> 4;    // 2 output rows each
        float acc[2][4] = {{0.f,0.f,0.f,0.f},{0.f,0.f,0.f,0.f}};

        const float4* w4 = reinterpret_cast<const float4*>(w);

        for (int k0 = 0; k0 < KDIM; k0 += 32) {
            #pragma unroll
            for (int s = 0; s < 4; s++) {
                int e  = s * 256 + t;
                int mm = e >> 5;
                int kk = e & 31;
                int m  = m0 + mm;
                int p  = m >> 2;
                int l  = m & 3;
                int py = l >> 1, px = l & 1;
                int k  = k0 + kk;
                int c  = k >> 8;
                int rem = k & 255;
                int ii = rem >> 4, jj = rem & 15;
                As[mm][kk] = prompt[((size_t)(p * 3 + c) * 32 + py * 16 + ii) * 32
                                    + px * 16 + jj];
            }
            #pragma unroll
            for (int s = 0; s < 2; s++) {
                int v  = s * 256 + t;        // 0..511
                int dd = v >> 3;             // 0..63
                int kv = v & 7;
                float4 f = w4[(size_t)(n0 + dd) * 192 + (k0 >> 2) + kv];
                Ws[dd][kv * 4 + 0] = f.x;
                Ws[dd][kv * 4 + 1] = f.y;
                Ws[dd][kv * 4 + 2] = f.z;
                Ws[dd][kv * 4 + 3] = f.w;
            }
            __syncthreads();
            #pragma unroll
            for (int kk = 0; kk < 32; kk++) {
                float a0 = As[ty * 2 + 0][kk];
                float a1 = As[ty * 2 + 1][kk];
                #pragma unroll
                for (int j = 0; j < 4; j++) {
                    float wv = Ws[tx * 4 + j][kk];
                    acc[0][j] += a0 * wv;
                    acc[1][j] += a1 * wv;
                }
            }
            __syncthreads();
        }
        #pragma unroll
        for (int r = 0; r < 2; r++) {
            #pragma unroll
            for (int j = 0; j < 4; j++) {
                int m = m0 + ty * 2 + r;
                int d = n0 + tx * 4 + j;
                g_pembed[m * DD + d] = acc[r][j] + bias[d];
            }
        }
    } else if (bx == 48) {
        // ---- prompt_key L2 normalize: 8 warps x 4 rows
        int warp = t >> 5, lane = t & 31;
        for (int p = warp; p < PP; p += 8) {
            const float* row = pkey + (size_t)p * DD;
            float sq = 0.f;
            for (int k = lane; k < DD; k += 32) { float v = row[k]; sq += v * v; }
            #pragma unroll
            for (int o = 16; o; o >>= 1) sq += __shfl_xor_sync(0xffffffffu, sq, o);
            float rs = rsqrtf(fmaxf(sq, 1e-12f));
            for (int k = lane; k < DD; k += 32) g_pnorm[p * DD + k] = row[k] * rs;
        }
    } else {
        // ---- copy x_embed row-block to output + accumulate mean (fused read)
        // Streaming hints: touch-once data, keep it out of L2's way.
        int b = bx - 49;
        if (t < 192) {
            const float4* src = reinterpret_cast<const float4*>(x)
                                + (size_t)b * NN * 192 + t;
            float4* dst = reinterpret_cast<float4*>(out)
                          + ((size_t)b * 216 + 20) * 192 + t;
            float4 acc = make_float4(0.f, 0.f, 0.f, 0.f);
            #pragma unroll 1
            for (int n = 0; n < NN; n += 7) {     // 196 = 28 * 7, deep MLP
                float4 v[7];
                #pragma unroll
                for (int u = 0; u < 7; u++) v[u] = __ldcs(&src[(size_t)(n + u) * 192]);
                #pragma unroll
                for (int u = 0; u < 7; u++) {
                    __stcs(&dst[(size_t)(n + u) * 192], v[u]);
                    acc.x += v[u].x; acc.y += v[u].y;
                    acc.z += v[u].z; acc.w += v[u].w;
                }
            }
            const float inv = 1.0f / 196.0f;
            acc.x *= inv; acc.y *= inv; acc.z *= inv; acc.w *= inv;
            reinterpret_cast<float4*>(g_mean)[(size_t)b * 192 + t] = acc;
        }
    }
}

// ---------------------------------------------------------------------------
// Fused tail: one block per batch row.
//   1. load mean row, compute rsqrt norm
//   2. sim[b,p] = rs * dot(mean, pnorm[p])  (8 warps x 4 pool entries)
//   3. warp-0 top-5 argmax (lower index wins ties), write idx (+float idx out)
//   4. gather 20 prompt-embed rows into out rows [0,20)  (L2-hot source)
//   5. deterministic reduce_sim: last block sums g_rs[0..255] in order
// ---------------------------------------------------------------------------
__global__ __launch_bounds__(256) void fused_tail_kernel(float* __restrict__ out)
{
    __shared__ float sx[DD];
    __shared__ float s_red[8];
    __shared__ float s_sim[PP];
    __shared__ int   s_idx[TOPK];
    __shared__ int   s_last;

    const int b = blockIdx.x, t = threadIdx.x;
    const int warp = t >> 5, lane = t & 31;
    const unsigned FULL = 0xffffffffu;

    // ---- load mean row + squared norm
    float sq = 0.f;
    for (int k = t; k < DD; k += 256) {
        float v = g_mean[(size_t)b * DD + k];
        sx[k] = v;
        sq += v * v;
    }
    #pragma unroll
    for (int o = 16; o; o >>= 1) sq += __shfl_xor_sync(FULL, sq, o);
    if (lane == 0) s_red[warp] = sq;
    __syncthreads();
    if (warp == 0) {
        float v = (lane < 8) ? s_red[lane] : 0.f;
        #pragma unroll
        for (int o = 4; o; o >>= 1) v += __shfl_xor_sync(FULL, v, o);
        if (lane == 0) s_red[0] = rsqrtf(fmaxf(v, 1e-12f));
    }
    __syncthreads();
    const float rs = s_red[0];

    // ---- similarity: warp w handles p = w, w+8, w+16, w+24
    for (int p = warp; p < PP; p += 8) {
        const float* pn = g_pnorm + (size_t)p * DD;
        float dot = 0.f;
        for (int k = lane; k < DD; k += 32) dot += sx[k] * pn[k];
        #pragma unroll
        for (int o = 16; o; o >>= 1) dot += __shfl_xor_sync(FULL, dot, o);
        if (lane == 0) {
            float s = dot * rs;
            s_sim[p] = s;
            out[O_SIM + (size_t)b * PP + p] = s;
        }
    }
    __syncthreads();

    // ---- top-5 (warp 0): argmax with lower-index tie-break
    if (warp == 0) {
        float v = s_sim[lane];
        unsigned sel = 0u;
        float lsum = 0.f;
        #pragma unroll
        for (int k = 0; k < TOPK; k++) {
            float bv = ((sel >> lane) & 1u) ? -__int_as_float(0x7f800000) : v;
            int   bi = lane;
            #pragma unroll
            for (int o = 16; o; o >>= 1) {
                float ov = __shfl_xor_sync(FULL, bv, o);
                int   oi = __shfl_xor_sync(FULL, bi, o);
                if (ov > bv || (ov == bv && oi < bi)) { bv = ov; bi = oi; }
            }
            sel |= 1u << bi;
            if (lane == 0) {
                s_idx[k] = bi;
                out[O_IDX + (size_t)b * TOPK + k] = (float)bi;
                lsum += bv;
            }
        }
        if (lane == 0) g_rs[b] = lsum;
    }
    __syncthreads();

    // ---- gather 20 rows (5 prompts x 4 patches) into out rows [0,20)
    const float4* pe4 = reinterpret_cast<const float4*>(g_pembed);
    float4* ob4 = reinterpret_cast<float4*>(out) + (size_t)b * 216 * 192;
    #pragma unroll
    for (int e = t; e < 20 * 192; e += 256) {
        int j = e / 192;          // output row 0..19
        int c = e - j * 192;      // float4 column
        int i = s_idx[j >> 2];    // selected prompt
        int row = i * 4 + (j & 3);
        ob4[(size_t)j * 192 + c] = pe4[(size_t)row * 192 + c];
    }

    // ---- deterministic reduce_sim: last arriving block sums in fixed order
    if (t == 0) {
        __threadfence();
        int old = atomicAdd(&g_counter, 1);
        s_last = (old == BB - 1);
    }
    __syncthreads();
    if (s_last) {
        __threadfence();
        float v = g_rs[t];
        #pragma unroll
        for (int o = 16; o; o >>= 1) v += __shfl_xor_sync(FULL, v, o);
        if (lane == 0) s_red[warp] = v;
        __syncthreads();
        if (t == 0) {
            float tot = 0.f;
            #pragma unroll
            for (int wv = 0; wv < 8; wv++) tot += s_red[wv];
            out[O_RS] = tot / (float)BB;
            g_counter = 0;                   // reset for next graph replay
        }
    }
}

// ---------------------------------------------------------------------------
extern "C" void kernel_launch(void* const* d_in, const int* in_sizes, int n_in,
                              void* d_out, int out_size)
{
    const float* x      = (const float*)d_in[0];  // x_embed  (256,196,768)
    const float* prompt = (const float*)d_in[1];  // prompt   (32,3,32,32)
    const float* pkey   = (const float*)d_in[2];  // prompt_key (32,768)
    const float* w      = (const float*)d_in[3];  // conv_w   (768,3,16,16)
    const float* bias   = (const float*)d_in[4];  // conv_b   (768)
    float* out = (float*)d_out;

    mega_kernel<<<49 + BB, 256>>>(x, prompt, pkey, w, bias, out);
    fused_tail_kernel<<<BB, 256>>>(out);
}

// round 4
// speedup vs baseline: 1.3524x; 1.0650x over previous
#include <cuda_runtime.h>

// Problem constants
#define BB   256   // batch
#define NN   196   // tokens
#define DD   768   // dim
#define PP   32    // pool size
#define TOPK 5
#define MM   128   // PP*4 rows of patch-embed GEMM
#define KDIM 768   // 3*16*16

// Output layout (flattened tuple, float32):
//   prompted_embedding (256,216,768) | reduce_sim (1) | similarity (256,32) | idx (256,5)
#define O_RS  (42467328ll)
#define O_SIM (O_RS + 1)          // NOTE: odd offset -> only 4B-aligned, scalar stores only
#define O_IDX (O_SIM + (long long)BB * PP)

// Scratch (static device globals — no allocation allowed)
__device__ float g_pembed[MM * DD];   // patch-embed result (128,768)
__device__ float g_mean[BB * DD];     // per-batch mean of x_embed
__device__ float g_pnorm[PP * DD];    // l2-normalized prompt_key
__device__ float g_rs[BB];            // per-batch top-5 sim sums
__device__ int   g_counter;           // last-block arrival counter (reset by winner)

// ---------------------------------------------------------------------------
// Mega kernel: three block roles. (measured ~6.1 TB/s — at LTS ceiling)
//   blocks [0,48):  patch-embed GEMM  (M=128,N=768,K=768), 32x64 tiles
//   block  48:      prompt_key L2 normalize
//   blocks [49,305): per-batch copy x_embed -> out rows [20,216) + mean accum
// ---------------------------------------------------------------------------
__global__ __launch_bounds__(256) void mega_kernel(
    const float* __restrict__ x,       // (256,196,768)
    const float* __restrict__ prompt,  // (32,3,32,32)
    const float* __restrict__ pkey,    // (32,768)
    const float* __restrict__ w,       // (768,3,16,16) == (768,768) row-major
    const float* __restrict__ bias,    // (768)
    float* __restrict__ out)
{
    const int bx = blockIdx.x;
    const int t  = threadIdx.x;

    if (bx < 48) {
        // ---- patch-embed GEMM: out[m,d] = sum_k A[m,k]*W[d,k] + bias[d]
        __shared__ float As[32][33];
        __shared__ float Ws[64][33];
        const int m0 = (bx / 12) * 32;
        const int n0 = (bx % 12) * 64;
        const int tx = t & 15;    // 4 output cols each
        const int ty = t >> 4;    // 2 output rows each
        float acc[2][4] = {{0.f,0.f,0.f,0.f},{0.f,0.f,0.f,0.f}};

        const float4* w4 = reinterpret_cast<const float4*>(w);

        for (int k0 = 0; k0 < KDIM; k0 += 32) {
            #pragma unroll
            for (int s = 0; s < 4; s++) {
                int e  = s * 256 + t;
                int mm = e >> 5;
                int kk = e & 31;
                int m  = m0 + mm;
                int p  = m >> 2;
                int l  = m & 3;
                int py = l >> 1, px = l & 1;
                int k  = k0 + kk;
                int c  = k >> 8;
                int rem = k & 255;
                int ii = rem >> 4, jj = rem & 15;
                As[mm][kk] = prompt[((size_t)(p * 3 + c) * 32 + py * 16 + ii) * 32
                                    + px * 16 + jj];
            }
            #pragma unroll
            for (int s = 0; s < 2; s++) {
                int v  = s * 256 + t;        // 0..511
                int dd = v >> 3;             // 0..63
                int kv = v & 7;
                float4 f = w4[(size_t)(n0 + dd) * 192 + (k0 >> 2) + kv];
                Ws[dd][kv * 4 + 0] = f.x;
                Ws[dd][kv * 4 + 1] = f.y;
                Ws[dd][kv * 4 + 2] = f.z;
                Ws[dd][kv * 4 + 3] = f.w;
            }
            __syncthreads();
            #pragma unroll
            for (int kk = 0; kk < 32; kk++) {
                float a0 = As[ty * 2 + 0][kk];
                float a1 = As[ty * 2 + 1][kk];
                #pragma unroll
                for (int j = 0; j < 4; j++) {
                    float wv = Ws[tx * 4 + j][kk];
                    acc[0][j] += a0 * wv;
                    acc[1][j] += a1 * wv;
                }
            }
            __syncthreads();
        }
        #pragma unroll
        for (int r = 0; r < 2; r++) {
            #pragma unroll
            for (int j = 0; j < 4; j++) {
                int m = m0 + ty * 2 + r;
                int d = n0 + tx * 4 + j;
                g_pembed[m * DD + d] = acc[r][j] + bias[d];
            }
        }
    } else if (bx == 48) {
        // ---- prompt_key L2 normalize: 8 warps x 4 rows
        int warp = t >> 5, lane = t & 31;
        for (int p = warp; p < PP; p += 8) {
            const float* row = pkey + (size_t)p * DD;
            float sq = 0.f;
            for (int k = lane; k < DD; k += 32) { float v = row[k]; sq += v * v; }
            #pragma unroll
            for (int o = 16; o; o >>= 1) sq += __shfl_xor_sync(0xffffffffu, sq, o);
            float rs = rsqrtf(fmaxf(sq, 1e-12f));
            for (int k = lane; k < DD; k += 32) g_pnorm[p * DD + k] = row[k] * rs;
        }
    } else {
        // ---- copy x_embed row-block to output + accumulate mean (fused read)
        int b = bx - 49;
        if (t < 192) {
            const float4* src = reinterpret_cast<const float4*>(x)
                                + (size_t)b * NN * 192 + t;
            float4* dst = reinterpret_cast<float4*>(out)
                          + ((size_t)b * 216 + 20) * 192 + t;
            float4 acc = make_float4(0.f, 0.f, 0.f, 0.f);
            #pragma unroll 1
            for (int n = 0; n < NN; n += 7) {     // 196 = 28 * 7, deep MLP
                float4 v[7];
                #pragma unroll
                for (int u = 0; u < 7; u++) v[u] = __ldcs(&src[(size_t)(n + u) * 192]);
                #pragma unroll
                for (int u = 0; u < 7; u++) {
                    __stcs(&dst[(size_t)(n + u) * 192], v[u]);
                    acc.x += v[u].x; acc.y += v[u].y;
                    acc.z += v[u].z; acc.w += v[u].w;
                }
            }
            const float inv = 1.0f / 196.0f;
            acc.x *= inv; acc.y *= inv; acc.z *= inv; acc.w *= inv;
            reinterpret_cast<float4*>(g_mean)[(size_t)b * 192 + t] = acc;
        }
    }
}

// ---------------------------------------------------------------------------
// Fused tail: one block per batch row. Sim loop interleaves 4 dots/warp with a
// fully unrolled k-loop so the L2 loads front-batch (MLP ~16+ instead of 1).
// ---------------------------------------------------------------------------
__global__ __launch_bounds__(256) void fused_tail_kernel(float* __restrict__ out)
{
    __shared__ float sx[DD];
    __shared__ float s_red[8];
    __shared__ float s_sim[PP];
    __shared__ int   s_idx[TOPK];
    __shared__ int   s_last;

    const int b = blockIdx.x, t = threadIdx.x;
    const int warp = t >> 5, lane = t & 31;
    const unsigned FULL = 0xffffffffu;

    // ---- load mean row + squared-norm partials
    float sq = 0.f;
    #pragma unroll
    for (int i = 0; i < 3; i++) {
        int k = t + i * 256;
        float v = g_mean[(size_t)b * DD + k];
        sx[k] = v;
        sq += v * v;
    }
    #pragma unroll
    for (int o = 16; o; o >>= 1) sq += __shfl_xor_sync(FULL, sq, o);
    if (lane == 0) s_red[warp] = sq;
    __syncthreads();

    // every warp computes rs itself (no extra block sync)
    float rv = (lane < 8) ? s_red[lane] : 0.f;
    #pragma unroll
    for (int o = 4; o; o >>= 1) rv += __shfl_xor_sync(FULL, rv, o);
    const float rs = rsqrtf(fmaxf(__shfl_sync(FULL, rv, 0), 1e-12f));

    // ---- similarity: warp w owns pool rows 4w..4w+3, interleaved dots
    {
        const float* __restrict__ pn0 = g_pnorm + (size_t)(warp * 4 + 0) * DD;
        const float* __restrict__ pn1 = g_pnorm + (size_t)(warp * 4 + 1) * DD;
        const float* __restrict__ pn2 = g_pnorm + (size_t)(warp * 4 + 2) * DD;
        const float* __restrict__ pn3 = g_pnorm + (size_t)(warp * 4 + 3) * DD;
        float d0 = 0.f, d1 = 0.f, d2 = 0.f, d3 = 0.f;
        #pragma unroll
        for (int i = 0; i < DD / 32; i++) {      // 24 iterations, fully unrolled
            int k = lane + i * 32;
            float xv = sx[k];
            d0 += xv * __ldg(pn0 + k);
            d1 += xv * __ldg(pn1 + k);
            d2 += xv * __ldg(pn2 + k);
            d3 += xv * __ldg(pn3 + k);
        }
        #pragma unroll
        for (int o = 16; o; o >>= 1) {
            d0 += __shfl_xor_sync(FULL, d0, o);
            d1 += __shfl_xor_sync(FULL, d1, o);
            d2 += __shfl_xor_sync(FULL, d2, o);
            d3 += __shfl_xor_sync(FULL, d3, o);
        }
        if (lane == 0) {
            int p = warp * 4;
            float v0 = d0 * rs, v1 = d1 * rs, v2 = d2 * rs, v3 = d3 * rs;
            s_sim[p + 0] = v0; s_sim[p + 1] = v1;
            s_sim[p + 2] = v2; s_sim[p + 3] = v3;
            // scalar stores: O_SIM is an odd float offset -> not 16B-aligned
            float* so = out + O_SIM + (size_t)b * PP + p;
            so[0] = v0; so[1] = v1; so[2] = v2; so[3] = v3;
        }
    }
    __syncthreads();

    // ---- top-5 (warp 0): iterative argmax, lower index wins ties
    if (warp == 0) {
        float v = s_sim[lane];
        unsigned sel = 0u;
        float lsum = 0.f;
        #pragma unroll
        for (int k = 0; k < TOPK; k++) {
            float bv = ((sel >> lane) & 1u) ? -__int_as_float(0x7f800000) : v;
            int   bi = lane;
            #pragma unroll
            for (int o = 16; o; o >>= 1) {
                float ov = __shfl_xor_sync(FULL, bv, o);
                int   oi = __shfl_xor_sync(FULL, bi, o);
                if (ov > bv || (ov == bv && oi < bi)) { bv = ov; bi = oi; }
            }
            sel |= 1u << bi;
            if (lane == 0) {
                s_idx[k] = bi;
                out[O_IDX + (size_t)b * TOPK + k] = (float)bi;
                lsum += bv;
            }
        }
        if (lane == 0) g_rs[b] = lsum;
    }
    __syncthreads();

    // ---- gather 20 rows (5 prompts x 4 patches) into out rows [0,20)
    const float4* pe4 = reinterpret_cast<const float4*>(g_pembed);
    float4* ob4 = reinterpret_cast<float4*>(out) + (size_t)b * 216 * 192;
    #pragma unroll
    for (int e = t; e < 20 * 192; e += 256) {
        int j = e / 192;          // output row 0..19
        int c = e - j * 192;      // float4 column
        int i = s_idx[j >> 2];    // selected prompt
        int row = i * 4 + (j & 3);
        ob4[(size_t)j * 192 + c] = pe4[(size_t)row * 192 + c];
    }

    // ---- deterministic reduce_sim: last arriving block sums in fixed order
    if (t == 0) {
        __threadfence();
        int old = atomicAdd(&g_counter, 1);
        s_last = (old == BB - 1);
    }
    __syncthreads();
    if (s_last) {
        __threadfence();
        float v = g_rs[t];
        #pragma unroll
        for (int o = 16; o; o >>= 1) v += __shfl_xor_sync(FULL, v, o);
        if (lane == 0) s_red[warp] = v;
        __syncthreads();
        if (t == 0) {
            float tot = 0.f;
            #pragma unroll
            for (int wv = 0; wv < 8; wv++) tot += s_red[wv];
            out[O_RS] = tot / (float)BB;
            g_counter = 0;                   // reset for next graph replay
        }
    }
}

// ---------------------------------------------------------------------------
extern "C" void kernel_launch(void* const* d_in, const int* in_sizes, int n_in,
                              void* d_out, int out_size)
{
    const float* x      = (const float*)d_in[0];  // x_embed  (256,196,768)
    const float* prompt = (const float*)d_in[1];  // prompt   (32,3,32,32)
    const float* pkey   = (const float*)d_in[2];  // prompt_key (32,768)
    const float* w      = (const float*)d_in[3];  // conv_w   (768,3,16,16)
    const float* bias   = (const float*)d_in[4];  // conv_b   (768)
    float* out = (float*)d_out;

    mega_kernel<<<49 + BB, 256>>>(x, prompt, pkey, w, bias, out);
    fused_tail_kernel<<<BB, 256>>>(out);
}

// round 5
// speedup vs baseline: 1.4256x; 1.0541x over previous
#include <cuda_runtime.h>

// Problem constants
#define BB   256   // batch
#define NN   196   // tokens
#define DD   768   // dim
#define PP   32    // pool size
#define TOPK 5
#define MM   128   // PP*4 rows of patch-embed GEMM
#define KDIM 768   // 3*16*16

// Output layout (flattened tuple, float32):
//   prompted_embedding (256,216,768) | reduce_sim (1) | similarity (256,32) | idx (256,5)
#define O_RS  (42467328ll)
#define O_SIM (O_RS + 1)          // odd float offset -> 4B-aligned only; scalar stores
#define O_IDX (O_SIM + (long long)BB * PP)

#define N_PRODUCERS 49            // 48 GEMM blocks + 1 pnorm block

// Scratch (static device globals — no allocation allowed)
__device__ float g_pembed[MM * DD];   // patch-embed result (128,768)
__device__ float g_pnorm[PP * DD];    // l2-normalized prompt_key
__device__ float g_rs[BB];            // per-batch top-5 sim sums
__device__ int   g_ready;             // producer completion counter
__device__ int   g_counter;           // tail completion counter

// ---------------------------------------------------------------------------
// Single fused kernel, three block roles:
//   blocks [0,48):   patch-embed GEMM -> g_pembed, then signal g_ready
//   block  48:       prompt_key L2 normalize -> g_pnorm, then signal g_ready
//   blocks [49,305): copy x_embed -> out rows[20,216), mean kept in SMEM,
//                    then spin on g_ready and run sim+top5+gather for batch b.
// All 305 blocks are co-resident (<=12.7KB smem, 256 thr), so the spin is safe.
// ---------------------------------------------------------------------------
__global__ __launch_bounds__(256) void fused_kernel(
    const float* __restrict__ x,       // (256,196,768)
    const float* __restrict__ prompt,  // (32,3,32,32)
    const float* __restrict__ pkey,    // (32,768)
    const float* __restrict__ w,       // (768,3,16,16) == (768,768) row-major
    const float* __restrict__ bias,    // (768)
    float* __restrict__ out)
{
    const int bx = blockIdx.x;
    const int t  = threadIdx.x;
    const int warp = t >> 5, lane = t & 31;
    const unsigned FULL = 0xffffffffu;

    if (bx < 48) {
        // ---- patch-embed GEMM: g_pembed[m,d] = sum_k A[m,k]*W[d,k] + bias[d]
        __shared__ float As[32][33];
        __shared__ float Ws[64][33];
        const int m0 = (bx / 12) * 32;
        const int n0 = (bx % 12) * 64;
        const int tx = t & 15;    // 4 output cols each
        const int ty = t >> 4;    // 2 output rows each
        float acc[2][4] = {{0.f,0.f,0.f,0.f},{0.f,0.f,0.f,0.f}};

        const float4* w4 = reinterpret_cast<const float4*>(w);

        for (int k0 = 0; k0 < KDIM; k0 += 32) {
            #pragma unroll
            for (int s = 0; s < 4; s++) {
                int e  = s * 256 + t;
                int mm = e >> 5;
                int kk = e & 31;
                int m  = m0 + mm;
                int p  = m >> 2;
                int l  = m & 3;
                int py = l >> 1, px = l & 1;
                int k  = k0 + kk;
                int c  = k >> 8;
                int rem = k & 255;
                int ii = rem >> 4, jj = rem & 15;
                As[mm][kk] = prompt[((size_t)(p * 3 + c) * 32 + py * 16 + ii) * 32
                                    + px * 16 + jj];
            }
            #pragma unroll
            for (int s = 0; s < 2; s++) {
                int v  = s * 256 + t;        // 0..511
                int dd = v >> 3;             // 0..63
                int kv = v & 7;
                float4 f = w4[(size_t)(n0 + dd) * 192 + (k0 >> 2) + kv];
                Ws[dd][kv * 4 + 0] = f.x;
                Ws[dd][kv * 4 + 1] = f.y;
                Ws[dd][kv * 4 + 2] = f.z;
                Ws[dd][kv * 4 + 3] = f.w;
            }
            __syncthreads();
            #pragma unroll
            for (int kk = 0; kk < 32; kk++) {
                float a0 = As[ty * 2 + 0][kk];
                float a1 = As[ty * 2 + 1][kk];
                #pragma unroll
                for (int j = 0; j < 4; j++) {
                    float wv = Ws[tx * 4 + j][kk];
                    acc[0][j] += a0 * wv;
                    acc[1][j] += a1 * wv;
                }
            }
            __syncthreads();
        }
        #pragma unroll
        for (int r = 0; r < 2; r++) {
            #pragma unroll
            for (int j = 0; j < 4; j++) {
                int m = m0 + ty * 2 + r;
                int d = n0 + tx * 4 + j;
                g_pembed[m * DD + d] = acc[r][j] + bias[d];
            }
        }
        // signal completion
        __syncthreads();
        __threadfence();
        if (t == 0) atomicAdd(&g_ready, 1);

    } else if (bx == 48) {
        // ---- prompt_key L2 normalize: 8 warps x 4 rows
        for (int p = warp; p < PP; p += 8) {
            const float* row = pkey + (size_t)p * DD;
            float sq = 0.f;
            for (int k = lane; k < DD; k += 32) { float v = row[k]; sq += v * v; }
            #pragma unroll
            for (int o = 16; o; o >>= 1) sq += __shfl_xor_sync(FULL, sq, o);
            float rs = rsqrtf(fmaxf(sq, 1e-12f));
            for (int k = lane; k < DD; k += 32) g_pnorm[p * DD + k] = row[k] * rs;
        }
        __syncthreads();
        __threadfence();
        if (t == 0) atomicAdd(&g_ready, 1);

    } else {
        // ================= copy + fused per-batch tail =================
        __shared__ float sx[DD];
        __shared__ float s_red[8];
        __shared__ float s_sim[PP];
        __shared__ int   s_idx[TOPK];
        __shared__ int   s_last;

        const int b = bx - N_PRODUCERS;

        // ---- copy x_embed rows -> out rows [20,216) + mean into SMEM
        if (t < 192) {
            const float4* src = reinterpret_cast<const float4*>(x)
                                + (size_t)b * NN * 192 + t;
            float4* dst = reinterpret_cast<float4*>(out)
                          + ((size_t)b * 216 + 20) * 192 + t;
            float4 acc = make_float4(0.f, 0.f, 0.f, 0.f);
            #pragma unroll 1
            for (int n = 0; n < NN; n += 7) {     // 196 = 28 * 7, deep MLP
                float4 v[7];
                #pragma unroll
                for (int u = 0; u < 7; u++) v[u] = __ldcs(&src[(size_t)(n + u) * 192]);
                #pragma unroll
                for (int u = 0; u < 7; u++) {
                    __stcs(&dst[(size_t)(n + u) * 192], v[u]);
                    acc.x += v[u].x; acc.y += v[u].y;
                    acc.z += v[u].z; acc.w += v[u].w;
                }
            }
            const float inv = 1.0f / 196.0f;
            acc.x *= inv; acc.y *= inv; acc.z *= inv; acc.w *= inv;
            reinterpret_cast<float4*>(sx)[t] = acc;
        }

        // ---- wait for GEMM + pnorm producers (all blocks co-resident: safe)
        if (t == 0) {
            while (atomicAdd(&g_ready, 0) < N_PRODUCERS) { }
        }
        __syncthreads();
        __threadfence();

        // ---- squared norm of mean (from SMEM)
        float sq = 0.f;
        #pragma unroll
        for (int i = 0; i < 3; i++) {
            int k = t + i * 256;
            float v = sx[k];
            sq += v * v;
        }
        #pragma unroll
        for (int o = 16; o; o >>= 1) sq += __shfl_xor_sync(FULL, sq, o);
        if (lane == 0) s_red[warp] = sq;
        __syncthreads();
        float rv = (lane < 8) ? s_red[lane] : 0.f;
        #pragma unroll
        for (int o = 4; o; o >>= 1) rv += __shfl_xor_sync(FULL, rv, o);
        const float rs = rsqrtf(fmaxf(__shfl_sync(FULL, rv, 0), 1e-12f));

        // ---- similarity: warp w owns pool rows 4w..4w+3, interleaved dots
        {
            const float* __restrict__ pn0 = g_pnorm + (size_t)(warp * 4 + 0) * DD;
            const float* __restrict__ pn1 = g_pnorm + (size_t)(warp * 4 + 1) * DD;
            const float* __restrict__ pn2 = g_pnorm + (size_t)(warp * 4 + 2) * DD;
            const float* __restrict__ pn3 = g_pnorm + (size_t)(warp * 4 + 3) * DD;
            float d0 = 0.f, d1 = 0.f, d2 = 0.f, d3 = 0.f;
            #pragma unroll
            for (int i = 0; i < DD / 32; i++) {      // fully unrolled -> MLP high
                int k = lane + i * 32;
                float xv = sx[k];
                d0 += xv * __ldg(pn0 + k);
                d1 += xv * __ldg(pn1 + k);
                d2 += xv * __ldg(pn2 + k);
                d3 += xv * __ldg(pn3 + k);
            }
            #pragma unroll
            for (int o = 16; o; o >>= 1) {
                d0 += __shfl_xor_sync(FULL, d0, o);
                d1 += __shfl_xor_sync(FULL, d1, o);
                d2 += __shfl_xor_sync(FULL, d2, o);
                d3 += __shfl_xor_sync(FULL, d3, o);
            }
            if (lane == 0) {
                int p = warp * 4;
                float v0 = d0 * rs, v1 = d1 * rs, v2 = d2 * rs, v3 = d3 * rs;
                s_sim[p + 0] = v0; s_sim[p + 1] = v1;
                s_sim[p + 2] = v2; s_sim[p + 3] = v3;
                float* so = out + O_SIM + (size_t)b * PP + p;   // 4B-aligned only
                so[0] = v0; so[1] = v1; so[2] = v2; so[3] = v3;
            }
        }
        __syncthreads();

        // ---- top-5 (warp 0): iterative argmax, lower index wins ties
        if (warp == 0) {
            float v = s_sim[lane];
            unsigned sel = 0u;
            float lsum = 0.f;
            #pragma unroll
            for (int k = 0; k < TOPK; k++) {
                float bv = ((sel >> lane) & 1u) ? -__int_as_float(0x7f800000) : v;
                int   bi = lane;
                #pragma unroll
                for (int o = 16; o; o >>= 1) {
                    float ov = __shfl_xor_sync(FULL, bv, o);
                    int   oi = __shfl_xor_sync(FULL, bi, o);
                    if (ov > bv || (ov == bv && oi < bi)) { bv = ov; bi = oi; }
                }
                sel |= 1u << bi;
                if (lane == 0) {
                    s_idx[k] = bi;
                    out[O_IDX + (size_t)b * TOPK + k] = (float)bi;
                    lsum += bv;
                }
            }
            if (lane == 0) g_rs[b] = lsum;
        }
        __syncthreads();

        // ---- gather 20 rows (5 prompts x 4 patches) into out rows [0,20)
        const float4* pe4 = reinterpret_cast<const float4*>(g_pembed);
        float4* ob4 = reinterpret_cast<float4*>(out) + (size_t)b * 216 * 192;
        #pragma unroll
        for (int e = t; e < 20 * 192; e += 256) {
            int j = e / 192;          // output row 0..19
            int c = e - j * 192;      // float4 column
            int i = s_idx[j >> 2];    // selected prompt
            int row = i * 4 + (j & 3);
            ob4[(size_t)j * 192 + c] = __ldg(pe4 + (size_t)row * 192 + c);
        }

        // ---- deterministic reduce_sim: last arriving block sums in order
        if (t == 0) {
            __threadfence();
            int old = atomicAdd(&g_counter, 1);
            s_last = (old == BB - 1);
        }
        __syncthreads();
        if (s_last) {
            __threadfence();
            float v = g_rs[t];
            #pragma unroll
            for (int o = 16; o; o >>= 1) v += __shfl_xor_sync(FULL, v, o);
            if (lane == 0) s_red[warp] = v;
            __syncthreads();
            if (t == 0) {
                float tot = 0.f;
                #pragma unroll
                for (int wv = 0; wv < 8; wv++) tot += s_red[wv];
                out[O_RS] = tot / (float)BB;
                g_counter = 0;                   // reset for next graph replay
                g_ready   = 0;
            }
        }
    }
}

// ---------------------------------------------------------------------------
extern "C" void kernel_launch(void* const* d_in, const int* in_sizes, int n_in,
                              void* d_out, int out_size)
{
    const float* x      = (const float*)d_in[0];  // x_embed  (256,196,768)
    const float* prompt = (const float*)d_in[1];  // prompt   (32,3,32,32)
    const float* pkey   = (const float*)d_in[2];  // prompt_key (32,768)
    const float* w      = (const float*)d_in[3];  // conv_w   (768,3,16,16)
    const float* bias   = (const float*)d_in[4];  // conv_b   (768)
    float* out = (float*)d_out;

    fused_kernel<<<N_PRODUCERS + BB, 256>>>(x, prompt, pkey, w, bias, out);
}